// round 4
// baseline (speedup 1.0000x reference)
#include <cuda_runtime.h>
#include <cstdint>

#define R  5
#define E  50000
#define NUx 20000
#define NIx 20000
#define NF 4
#define DN 16
#define DR 64
#define DO 64
// TAU = 0.5 -> 1/TAU = 2.0f

// ---------------- scratch (device globals; no allocation) ----------------
__device__ __align__(16) float g_blended[R * E];
__device__ __align__(16) float g_norm_user[NUx];
__device__ __align__(16) float g_norm_item[NIx];
__device__ __align__(16) float g_hu[R * NUx * DN];
__device__ __align__(16) float g_hi[R * NIx * DN];
__device__ __align__(16) float g_user_msg[NUx * DN];
__device__ __align__(16) float g_item_msg[NIx * DN];
// per-r weighted review-feature accumulators (the matvec-elimination trick)
__device__ __align__(16) float g_t_user[R * NUx * DR];
__device__ __align__(16) float g_t_item[R * NIx * DR];

__device__ __forceinline__ float dot4(float4 a, float4 b) {
    return a.x * b.x + a.y * b.y + a.z * b.z + a.w * b.w;
}

// vector global reduction (sm_90+): 4 floats in one RED
__device__ __forceinline__ void red_add_v4(float* p, float4 m) {
    asm volatile("red.global.add.v4.f32 [%0], {%1, %2, %3, %4};"
                 :: "l"(p), "f"(m.x), "f"(m.y), "f"(m.z), "f"(m.w)
                 : "memory");
}

// ---------------- kernel 1: zero accumulators (vectorized) ----------------
__global__ void zero_kernel() {
    int i = blockIdx.x * blockDim.x + threadIdx.x;
    float4 z = make_float4(0.f, 0.f, 0.f, 0.f);
    if (i < R * NUx * DR / 4) {
        reinterpret_cast<float4*>(g_t_user)[i] = z;
        reinterpret_cast<float4*>(g_t_item)[i] = z;
    }
    if (i < NUx * DN / 4) {
        reinterpret_cast<float4*>(g_user_msg)[i] = z;
        reinterpret_cast<float4*>(g_item_msg)[i] = z;
    }
    if (i < NUx / 4) {
        reinterpret_cast<float4*>(g_norm_user)[i] = z;
        reinterpret_cast<float4*>(g_norm_item)[i] = z;
    }
}

// ---------------- kernel 2: hu = uh @ Wfwd^T, hi = ih @ Wrev^T ----------------
__global__ void proj_kernel(const float* __restrict__ user_h,
                            const float* __restrict__ item_h,
                            const float* __restrict__ w_fwd,
                            const float* __restrict__ w_rev,
                            const int* __restrict__ kptr) {
    int idx = blockIdx.x * blockDim.x + threadIdx.x;
    if (idx >= R * NUx) return;
    int side = blockIdx.y;
    int r = idx / NUx, n = idx % NUx;
    int kk = *kptr;

    const float* h = (side ? item_h : user_h) + ((size_t)(kk * R + r) * NUx + n) * DN;
    const float* W = (side ? w_rev : w_fwd) + r * DN * DN;
    float* out = (side ? g_hi : g_hu) + ((size_t)r * NUx + n) * DN;

    float x[DN];
#pragma unroll
    for (int i = 0; i < 4; i++) {
        float4 t = reinterpret_cast<const float4*>(h)[i];
        x[4*i+0] = t.x; x[4*i+1] = t.y; x[4*i+2] = t.z; x[4*i+3] = t.w;
    }
#pragma unroll
    for (int o = 0; o < DN; o++) {
        float acc = 0.f;
#pragma unroll
        for (int d = 0; d < DN; d++) acc += x[d] * __ldg(&W[o * DN + d]);
        out[o] = acc;
    }
}

// ---------------- kernel 3: per-edge blended weight (thread per edge, no shfl) ----------------
__global__ void blend_kernel(const float* __restrict__ user_h,
                             const float* __restrict__ item_h,
                             const float* __restrict__ user_hsum,
                             const float* __restrict__ item_hsum,
                             const float* __restrict__ review_feat,
                             const float* __restrict__ prototypes,
                             const float* __restrict__ eta,
                             const int* __restrict__ edge_src,
                             const int* __restrict__ edge_dst,
                             const int* __restrict__ kptr) {
    __shared__ float4 sproto[NF * DR / 4];   // 64 float4
    int tid = threadIdx.x;
    if (tid < NF * DR / 4) sproto[tid] = reinterpret_cast<const float4*>(prototypes)[tid];
    __syncthreads();

    int r = blockIdx.y;
    int e = blockIdx.x * blockDim.x + tid;
    if (e >= E) return;
    int kk = *kptr;

    int src = edge_src[r * E + e];
    int dst = edge_dst[r * E + e];

    // cosine sim between l2-normalized user_h[k]/item_h[k] rows
    const float4* u4 = reinterpret_cast<const float4*>(
        user_h + ((size_t)(kk * R + r) * NUx + src) * DN);
    const float4* v4 = reinterpret_cast<const float4*>(
        item_h + ((size_t)(kk * R + r) * NIx + dst) * DN);
    float uu = 0.f, vv = 0.f, uv = 0.f;
#pragma unroll
    for (int i = 0; i < 4; i++) {
        float4 a = u4[i], b = v4[i];
        uu += dot4(a, a); vv += dot4(b, b); uv += dot4(a, b);
    }
    float nu_ = fmaxf(sqrtf(uu), 1e-12f);
    float nv_ = fmaxf(sqrtf(vv), 1e-12f);
    float sim_k = 2.f * uv / (nu_ * nv_);

    // sim_all denominator over NF=4 factors
    const float4* ra = reinterpret_cast<const float4*>(
        user_hsum + (size_t)(r * NUx + src) * (NF * DN));
    const float4* ca = reinterpret_cast<const float4*>(
        item_hsum + (size_t)(r * NIx + dst) * (NF * DN));
    float denom_sim = 0.f;
#pragma unroll
    for (int f = 0; f < NF; f++) {
        float p = 0.f;
#pragma unroll
        for (int d = 0; d < 4; d++) p += dot4(ra[f * 4 + d], ca[f * 4 + d]);
        denom_sim += __expf(2.f * p);
    }
    float exp_sim = __expf(sim_k) / denom_sim;

    // anchor softmax over prototypes (streams the full 1KB rf row)
    const float4* rf = reinterpret_cast<const float4*>(
        review_feat + ((size_t)r * E + e) * (NF * DR));
    float denom_a = 0.f, ak = 0.f;
#pragma unroll
    for (int f = 0; f < NF; f++) {
        float a = 0.f;
#pragma unroll
        for (int j = 0; j < DR / 4; j++) a += dot4(rf[f * (DR / 4) + j], sproto[f * (DR / 4) + j]);
        a *= 2.f;
        denom_a += __expf(a);
        if (f == kk) ak = a;
    }
    float exp_anchor = __expf(ak) / denom_a;

    float gsig = 1.f / (1.f + __expf(-eta[r * E + e]));
    float blended = gsig * exp_anchor + (1.f - gsig) * exp_sim;

    g_blended[r * E + e] = blended;
    atomicAdd(&g_norm_user[src], blended);
    atomicAdd(&g_norm_item[dst], blended);
}

// ---------------- kernel 4: normalize + scatter (thread per edge) ----------------
// t_item[r,dst] += w*rf_k ; t_user[r,src] += w*rf_k ;
// item_msg[dst] += w*hu[r,src] ; user_msg[src] += w*hi[r,dst]
__global__ void scatter_kernel(const float* __restrict__ review_feat,
                               const int* __restrict__ edge_src,
                               const int* __restrict__ edge_dst,
                               const int* __restrict__ kptr,
                               float* __restrict__ out_int_dist) {
    int r = blockIdx.y;
    int e = blockIdx.x * blockDim.x + threadIdx.x;
    if (e >= E) return;

    int src = edge_src[r * E + e];
    int dst = edge_dst[r * E + e];
    float w = g_blended[r * E + e] * rsqrtf(g_norm_user[src] * g_norm_item[dst]);
    out_int_dist[r * E + e] = w;

    int kk = *kptr;
    const float4* rf4 = reinterpret_cast<const float4*>(
        review_feat + (((size_t)r * E + e) * NF + kk) * DR);
    float* tu = g_t_user + ((size_t)r * NUx + src) * DR;
    float* ti = g_t_item + ((size_t)r * NIx + dst) * DR;
#pragma unroll
    for (int j = 0; j < DR / 4; j++) {
        float4 x = rf4[j];
        float4 v = make_float4(x.x * w, x.y * w, x.z * w, x.w * w);
        red_add_v4(ti + 4 * j, v);
        red_add_v4(tu + 4 * j, v);
    }

    const float4* hu4 = reinterpret_cast<const float4*>(g_hu + ((size_t)r * NUx + src) * DN);
    const float4* hi4 = reinterpret_cast<const float4*>(g_hi + ((size_t)r * NIx + dst) * DN);
    float* im = g_item_msg + (size_t)dst * DN;
    float* um = g_user_msg + (size_t)src * DN;
#pragma unroll
    for (int i = 0; i < 4; i++) {
        float4 h = hu4[i];
        red_add_v4(im + 4 * i, make_float4(h.x * w, h.y * w, h.z * w, h.w * w));
        float4 h2 = hi4[i];
        red_add_v4(um + 4 * i, make_float4(h2.x * w, h2.y * w, h2.z * w, h2.w * w));
    }
}

// ---------------- kernel 5: msg += t[r] @ W[r]^T (per-node matvec, 2 nodes/thread) ----------------
// grid: (ceil(NN/512), 2 sides, R)
__global__ void tmat_kernel(const float* __restrict__ rw_fwd,
                            const float* __restrict__ rw_rev) {
    __shared__ float4 sW[DN * DR / 4];   // one 16x64 weight matrix
    int side = blockIdx.y;               // 0 = user (uses W_rev), 1 = item (uses W_fwd)
    int r = blockIdx.z;
    int tid = threadIdx.x;

    const float4* W4 = reinterpret_cast<const float4*>(
        (side ? rw_fwd : rw_rev) + r * DN * DR);
    if (tid < DN * DR / 4) sW[tid] = W4[tid];
    __syncthreads();

    int n0 = blockIdx.x * 512 + tid;
    int n1 = n0 + 256;
    bool v0 = n0 < NUx, v1 = n1 < NUx;

    const float* t = (side ? g_t_item : g_t_user) + (size_t)r * NUx * DR;
    float* msg = side ? g_item_msg : g_user_msg;

    const float4* t0 = reinterpret_cast<const float4*>(t + (size_t)n0 * DR);
    const float4* t1 = reinterpret_cast<const float4*>(t + (size_t)n1 * DR);

    float acc0[DN], acc1[DN];
#pragma unroll
    for (int o = 0; o < DN; o++) { acc0[o] = 0.f; acc1[o] = 0.f; }

    float4 z = make_float4(0.f, 0.f, 0.f, 0.f);
#pragma unroll
    for (int d4 = 0; d4 < DR / 4; d4++) {
        float4 x0 = v0 ? t0[d4] : z;
        float4 x1 = v1 ? t1[d4] : z;
#pragma unroll
        for (int o = 0; o < DN; o++) {
            float4 wv = sW[o * (DR / 4) + d4];   // warp-uniform broadcast
            acc0[o] += dot4(x0, wv);
            acc1[o] += dot4(x1, wv);
        }
    }
    if (v0) {
#pragma unroll
        for (int i = 0; i < 4; i++)
            red_add_v4(msg + (size_t)n0 * DN + 4 * i,
                       make_float4(acc0[4*i], acc0[4*i+1], acc0[4*i+2], acc0[4*i+3]));
    }
    if (v1) {
#pragma unroll
        for (int i = 0; i < 4; i++)
            red_add_v4(msg + (size_t)n1 * DN + 4 * i,
                       make_float4(acc1[4*i], acc1[4*i+1], acc1[4*i+2], acc1[4*i+3]));
    }
}

// ---------------- kernel 6: leaky_relu + FC for users and items ----------------
__global__ void fc_kernel(const float* __restrict__ ufc_w, const float* __restrict__ ufc_b,
                          const float* __restrict__ ifc_w, const float* __restrict__ ifc_b,
                          float* __restrict__ out) {
    __shared__ float sW[2][DO * DN];
    __shared__ float sB[2][DO];
    int tid = threadIdx.x;   // 256
    for (int i = tid; i < DO * DN; i += 256) { sW[0][i] = ufc_w[i]; sW[1][i] = ifc_w[i]; }
    if (tid < DO) { sB[0][tid] = ufc_b[tid]; sB[1][tid] = ifc_b[tid]; }
    __syncthreads();

    int node = blockIdx.x * (256 / DO) + tid / DO;
    int o = tid % DO;
    if (node >= NUx + NIx) return;
    int side = node >= NUx;
    int n = side ? node - NUx : node;
    const float* msg = (side ? g_item_msg : g_user_msg) + (size_t)n * DN;

    float acc = sB[side][o];
#pragma unroll
    for (int d = 0; d < DN; d++) {
        float m = msg[d];
        m = (m >= 0.f) ? m : 0.1f * m;
        acc += m * sW[side][o * DN + d];
    }
    out[(size_t)node * DO + o] = acc;
}

// ---------------- launch ----------------
extern "C" void kernel_launch(void* const* d_in, const int* in_sizes, int n_in,
                              void* d_out, int out_size) {
    const float* user_h      = (const float*)d_in[0];
    const float* item_h      = (const float*)d_in[1];
    const float* user_hsum   = (const float*)d_in[2];
    const float* item_hsum   = (const float*)d_in[3];
    const float* review_feat = (const float*)d_in[4];
    const float* prototypes  = (const float*)d_in[5];
    const float* eta         = (const float*)d_in[6];
    const float* node_w_fwd  = (const float*)d_in[7];
    const float* review_w_fwd= (const float*)d_in[8];
    const float* node_w_rev  = (const float*)d_in[9];
    const float* review_w_rev= (const float*)d_in[10];
    const float* ufc_w       = (const float*)d_in[11];
    const float* ufc_b       = (const float*)d_in[12];
    const float* ifc_w       = (const float*)d_in[13];
    const float* ifc_b       = (const float*)d_in[14];
    const int*   edge_src    = (const int*)d_in[15];
    const int*   edge_dst    = (const int*)d_in[16];
    const int*   kptr        = (const int*)d_in[17];

    float* out = (float*)d_out;
    float* out_int = out + (size_t)(NUx + NIx) * DO;   // int_dist after ufeat+ifeat

    zero_kernel<<<(R * NUx * DR / 4 + 255) / 256, 256>>>();

    dim3 gp((R * NUx + 255) / 256, 2);
    proj_kernel<<<gp, 256>>>(user_h, item_h, node_w_fwd, node_w_rev, kptr);

    dim3 gb((E + 255) / 256, R);
    blend_kernel<<<gb, 256>>>(user_h, item_h, user_hsum, item_hsum,
                              review_feat, prototypes, eta,
                              edge_src, edge_dst, kptr);

    scatter_kernel<<<gb, 256>>>(review_feat, edge_src, edge_dst, kptr, out_int);

    dim3 gt((NUx + 511) / 512, 2, R);
    tmat_kernel<<<gt, 256>>>(review_w_fwd, review_w_rev);

    fc_kernel<<<((NUx + NIx) * DO) / 256, 256>>>(ufc_w, ufc_b, ifc_w, ifc_b, out);
}